// round 16
// baseline (speedup 1.0000x reference)
#include <cuda_runtime.h>
#include <math.h>
#include <stdint.h>

#define BATCH 4
#define SEQ 1024
#define DMODEL 2048
#define KVD 512
#define NHEADS 16
#define NGROUPS 4
#define HDIM 128
#define ROWS (BATCH*SEQ)           // 4096
#define SOFTMAX_SCALE 0.08838834764831845f   // 1/sqrt(128)

// ---------------------------------------------------------------------------
// Device scratch (no allocation allowed)
// ---------------------------------------------------------------------------
__device__ float g_Q[ROWS*DMODEL];     // 32 MB
__device__ float g_K[ROWS*KVD];        // 8 MB
__device__ float g_V[ROWS*KVD];        // 8 MB
__device__ float g_Vt[BATCH*NGROUPS*HDIM*SEQ]; // 8 MB  [b,g][dim][seq]
__device__ float g_O[ROWS*DMODEL];     // 32 MB (rounded-x before attention, O after)
__device__ float g_WqT[DMODEL*DMODEL]; // 16 MB  [N][K]
__device__ float g_WkT[KVD*DMODEL];    // 4 MB
__device__ float g_WvT[KVD*DMODEL];    // 4 MB
__device__ float g_WoT[DMODEL*DMODEL]; // 16 MB

// ---------------------------------------------------------------------------
// PTX helpers (sm_80-class only — NO tcgen05, harness targets bare sm_103)
// ---------------------------------------------------------------------------
__device__ __forceinline__ uint32_t smem_u32(const void* p) {
    uint32_t a;
    asm("{ .reg .u64 t; cvta.to.shared.u64 t, %1; cvt.u32.u64 %0, t; }"
        : "=r"(a) : "l"(p));
    return a;
}

__device__ __forceinline__ void cp16(uint32_t dst, const void* src) {
    asm volatile("cp.async.cg.shared.global [%0], [%1], 16;" :: "r"(dst), "l"(src));
}

__device__ __forceinline__ float f2tf32(float x) {
    uint32_t u = __float_as_uint(x);
    asm("cvt.rna.tf32.f32 %0, %0;" : "+r"(u));
    return __uint_as_float(u);
}

#define LDSM_X4(r0, r1, r2, r3, addr) \
    asm volatile("ldmatrix.sync.aligned.m8n8.x4.shared.b16 {%0,%1,%2,%3}, [%4];" \
        : "=r"(r0), "=r"(r1), "=r"(r2), "=r"(r3) : "r"(addr))

#define MMA_TF32(d, a0, a1, a2, a3, b0, b1) \
    asm volatile("mma.sync.aligned.m16n8k8.row.col.f32.tf32.tf32.f32 " \
        "{%0,%1,%2,%3}, {%4,%5,%6,%7}, {%8,%9}, {%0,%1,%2,%3};" \
        : "+f"((d)[0]), "+f"((d)[1]), "+f"((d)[2]), "+f"((d)[3]) \
        : "r"(a0), "r"(a1), "r"(a2), "r"(a3), "r"(b0), "r"(b1))

// ---------------------------------------------------------------------------
// Fused prep: 4 weight transposes (tf32-rounded) + x round-copy, ONE launch.
// Block layout: 32x8 threads. Block ranges:
//   [0,4096)      Wq  [2048][2048] -> WqT
//   [4096,5120)   Wk  [2048][512]  -> WkT
//   [5120,6144)   Wv  [2048][512]  -> WvT
//   [6144,10240)  Wo  [2048][2048] -> WoT
//   [10240,12288) x round-copy -> g_O (1024 float4 per block)
// ---------------------------------------------------------------------------
__device__ __forceinline__ void transpose_block(
    const float* __restrict__ in, float* __restrict__ out,
    int R, int C, int cb, int rb)
{
    __shared__ float t[32][33];
    int c0 = cb * 32, r0 = rb * 32;
    int x = threadIdx.x, y = threadIdx.y;
#pragma unroll
    for (int i = 0; i < 32; i += 8)
        t[y + i][x] = in[(size_t)(r0 + y + i) * C + c0 + x];
    __syncthreads();
#pragma unroll
    for (int i = 0; i < 32; i += 8)
        out[(size_t)(c0 + y + i) * R + r0 + x] = f2tf32(t[x][y + i]);
}

__global__ void prep_kernel(
    const float* __restrict__ x,
    const float* __restrict__ Wq, const float* __restrict__ Wk,
    const float* __restrict__ Wv, const float* __restrict__ Wo,
    float* __restrict__ xr,
    float* __restrict__ WqT, float* __restrict__ WkT,
    float* __restrict__ WvT, float* __restrict__ WoT)
{
    int bid = blockIdx.x;
    if (bid < 4096) {
        transpose_block(Wq, WqT, DMODEL, DMODEL, bid & 63, bid >> 6);
    } else if (bid < 5120) {
        int b = bid - 4096;
        transpose_block(Wk, WkT, DMODEL, KVD, b & 15, b >> 4);
    } else if (bid < 6144) {
        int b = bid - 5120;
        transpose_block(Wv, WvT, DMODEL, KVD, b & 15, b >> 4);
    } else if (bid < 10240) {
        int b = bid - 6144;
        transpose_block(Wo, WoT, DMODEL, DMODEL, b & 63, b >> 6);
    } else {
        int b = bid - 10240;                       // 0..2047
        int tid = threadIdx.y * 32 + threadIdx.x;  // 0..255
        const float4* src = (const float4*)x;
        float4* dst = (float4*)xr;
#pragma unroll
        for (int i = 0; i < 4; i++) {
            int idx = b * 1024 + i * 256 + tid;
            float4 v = src[idx];
            v.x = f2tf32(v.x); v.y = f2tf32(v.y);
            v.z = f2tf32(v.z); v.w = f2tf32(v.w);
            dst[idx] = v;
        }
    }
}

// ---------------------------------------------------------------------------
// V transpose: g_V [4096][512] -> g_Vt [b,g][128 dim][1024 seq]
// ---------------------------------------------------------------------------
__global__ void v_transpose_kernel(const float* __restrict__ in, float* __restrict__ out)
{
    __shared__ float t[32][33];
    int c0 = blockIdx.x * 32, r0 = blockIdx.y * 32;
    int x = threadIdx.x, y = threadIdx.y;  // 32 x 8
#pragma unroll
    for (int i = 0; i < 32; i += 8)
        t[y + i][x] = in[(size_t)(r0 + y + i) * KVD + c0 + x];
    __syncthreads();
#pragma unroll
    for (int i = 0; i < 32; i += 8) {
        int c = c0 + y + i;        // global col: g = c>>7, d = c&127
        int r = r0 + x;            // global row: b = r>>10, s = r&1023
        out[(((size_t)(r >> 10) * NGROUPS + (c >> 7)) * HDIM + (c & 127)) * SEQ + (r & 1023)]
            = t[x][y + i];
    }
}

// ---------------------------------------------------------------------------
// tf32 mma.sync GEMM: C[M,N] = A[M,K] @ BT[N,K]^T + bias
// mode: 0 = plain fp32 out; 1 = tf32-rounded out; 2 = RoPE(+rope_scale)+tf32 out
// ---------------------------------------------------------------------------
#define GM_SMEM 65536

__global__ __launch_bounds__(256) void tf32_mma_gemm(
    const float* __restrict__ A, const float* __restrict__ BT,
    const float* __restrict__ bias, float* __restrict__ C,
    int M, int N, int K, int mode, float rope_scale)
{
    extern __shared__ char sm[];
    const uint32_t sb = smem_u32(sm);
    const int tid = threadIdx.x;
    const int wid = tid >> 5, lid = tid & 31;
    const int bm = blockIdx.y * 128;
    const int bn = blockIdx.x * 128;
    const int wm = (wid >> 2) * 64;
    const int wn = (wid & 3) * 32;

    const uint32_t xr     = lid & 7;
    const uint32_t a_row  = wm + (lid & 15);
    const uint32_t a_cadd = (lid >= 16) ? 4u : 0u;
    const uint32_t b_row  = wn + ((lid >> 4) << 3) + (lid & 7);
    const uint32_t b_cadd = ((lid >> 3) & 1) * 4u;

    float acc[4][4][4];
#pragma unroll
    for (int mi = 0; mi < 4; mi++)
#pragma unroll
        for (int nj = 0; nj < 4; nj++)
#pragma unroll
            for (int r = 0; r < 4; r++) acc[mi][nj][r] = 0.f;

    const int nk = K >> 5;

    auto load_tile = [&](int buf, int ks) {
        const uint32_t abuf = sb + buf * 32768;
        const uint32_t bbuf = abuf + 16384;
        const int k0 = ks * 32;
#pragma unroll
        for (int it = 0; it < 8; it++) {
            int idx = tid + it * 256;
            int c = idx & 7;
            if (idx < 1024) {
                int row = idx >> 3;
                cp16(abuf + row * 128 + ((c ^ (row & 7)) << 4),
                     A + (size_t)(bm + row) * K + k0 + c * 4);
            } else {
                int row = (idx - 1024) >> 3;
                cp16(bbuf + row * 128 + ((c ^ (row & 7)) << 4),
                     BT + (size_t)(bn + row) * K + k0 + c * 4);
            }
        }
        asm volatile("cp.async.commit_group;" ::: "memory");
    };

    load_tile(0, 0);

    for (int ks = 0; ks < nk; ks++) {
        const int buf = ks & 1;
        if (ks + 1 < nk) {
            load_tile(buf ^ 1, ks + 1);
            asm volatile("cp.async.wait_group 1;" ::: "memory");
        } else {
            asm volatile("cp.async.wait_group 0;" ::: "memory");
        }
        __syncthreads();

        const uint32_t abase = sb + buf * 32768;
        const uint32_t bbase = abase + 16384;

#pragma unroll
        for (int s = 0; s < 4; s++) {
            const int k0 = s * 8;
            uint32_t ar[4][4];
#pragma unroll
            for (int mi = 0; mi < 4; mi++) {
                uint32_t addr = abase + (a_row + mi * 16) * 128
                              + ((((k0 + a_cadd) >> 2) ^ xr) << 4);
                LDSM_X4(ar[mi][0], ar[mi][1], ar[mi][2], ar[mi][3], addr);
            }
            uint32_t br[2][4];
#pragma unroll
            for (int nb = 0; nb < 2; nb++) {
                uint32_t addr = bbase + (b_row + nb * 16) * 128
                              + ((((k0 + b_cadd) >> 2) ^ xr) << 4);
                LDSM_X4(br[nb][0], br[nb][1], br[nb][2], br[nb][3], addr);
            }
#pragma unroll
            for (int mi = 0; mi < 4; mi++)
#pragma unroll
                for (int nj = 0; nj < 4; nj++) {
                    uint32_t b0 = br[nj >> 1][(nj & 1) * 2];
                    uint32_t b1 = br[nj >> 1][(nj & 1) * 2 + 1];
                    MMA_TF32(acc[mi][nj], ar[mi][0], ar[mi][1], ar[mi][2], ar[mi][3], b0, b1);
                }
        }
        __syncthreads();
    }

    const int tq = lid >> 2;
    const int tc = (lid & 3) * 2;
#pragma unroll
    for (int mi = 0; mi < 4; mi++) {
        const int row = bm + wm + mi * 16 + tq;
#pragma unroll
        for (int nj = 0; nj < 4; nj++) {
            const int col = bn + wn + nj * 8 + tc;   // always even
            float2 bv = *(const float2*)(bias + col);
            float2 o0 = { acc[mi][nj][0] + bv.x, acc[mi][nj][1] + bv.y };
            float2 o1 = { acc[mi][nj][2] + bv.x, acc[mi][nj][3] + bv.y };
            if (mode == 2) {
                int i = (col & 127) >> 1;
                float freq = exp2f(-((float)(2 * i) / 128.0f) * 13.287712379549449f);
                float s0, c0, s1, c1;
                sincosf((float)(row & (SEQ - 1)) * freq, &s0, &c0);
                sincosf((float)((row + 8) & (SEQ - 1)) * freq, &s1, &c1);
                float x0 = o0.x, y0 = o0.y, x1 = o1.x, y1 = o1.y;
                o0.x = (x0 * c0 - y0 * s0) * rope_scale;
                o0.y = (x0 * s0 + y0 * c0) * rope_scale;
                o1.x = (x1 * c1 - y1 * s1) * rope_scale;
                o1.y = (x1 * s1 + y1 * c1) * rope_scale;
            }
            if (mode != 0) {
                o0.x = f2tf32(o0.x); o0.y = f2tf32(o0.y);
                o1.x = f2tf32(o1.x); o1.y = f2tf32(o1.y);
            }
            *(float2*)(C + (size_t)row * N + col)       = o0;
            *(float2*)(C + (size_t)(row + 8) * N + col) = o1;
        }
    }
}

// ---------------------------------------------------------------------------
// Tensor-core flash attention, BM=128 q-rows per CTA, 512 threads / 16 warps.
// Smem: Qs 128x512B @0; Ks 64x512B x2; Vt 128x256B x2; Ss 128x256B; stats
// Warps: 4(M) x 4(N). S warp-tile 32x16; PV warp-tile 32x32.
// ---------------------------------------------------------------------------
#define AS_QS 0
#define AS_KS0 65536
#define AS_KS1 98304
#define AS_VS0 131072
#define AS_VS1 163840
#define AS_SS 196608
#define AS_STAT 229376
#define ATT_SMEM (AS_STAT + 1536)   // 230912 bytes

__global__ __launch_bounds__(512, 1) void attn_mma_kernel()
{
    extern __shared__ char smb[];
    const uint32_t sb = smem_u32(smb);
    float* row_m = (float*)(smb + AS_STAT);
    float* row_l = row_m + 128;
    float* row_f = row_l + 128;

    const int tid = threadIdx.x;
    const int wid = tid >> 5, lid = tid & 31;
    const int b = blockIdx.x >> 4;
    const int h = blockIdx.x & 15;
    const int g = h >> 2;
    const int q0 = blockIdx.y * 128;

    const float* Qg  = g_Q + (size_t)(b * SEQ + q0) * DMODEL + h * HDIM;
    const float* Kg  = g_K + (size_t)(b * SEQ) * KVD + g * HDIM;
    const float* Vtg = g_Vt + ((size_t)(b * NGROUPS + g)) * HDIM * SEQ;

    const uint32_t KSo[2] = {sb + AS_KS0, sb + AS_KS1};
    const uint32_t VSo[2] = {sb + AS_VS0, sb + AS_VS1};

    if (tid < 128) { row_m[tid] = -INFINITY; row_l[tid] = 0.f; }

    // Q: 128 rows x 512B swizzled (4096 chunks / 512 thr = 8 each)
#pragma unroll
    for (int it = 0; it < 8; it++) {
        int idx = tid + it * 512;
        int r = idx >> 5, c = idx & 31;
        cp16(sb + AS_QS + r * 512 + ((c ^ (r & 7)) << 4),
             Qg + (size_t)r * DMODEL + c * 4);
    }
    auto loadKV = [&](int buf, int t) {
        const float* Kt = Kg + (size_t)(t * 64) * KVD;
        const float* Vt = Vtg + t * 64;
#pragma unroll
        for (int it = 0; it < 4; it++) {
            int idx = tid + it * 512;
            int r = idx >> 5, c = idx & 31;
            cp16(KSo[buf] + r * 512 + ((c ^ (r & 7)) << 4),
                 Kt + (size_t)r * KVD + c * 4);
        }
#pragma unroll
        for (int it = 0; it < 4; it++) {
            int idx = tid + it * 512;
            int r = idx >> 4, c = idx & 15;
            cp16(VSo[buf] + r * 256 + (((uint32_t)c ^ (r & 7)) << 4),
                 Vt + (size_t)r * SEQ + c * 4);
        }
    };
    loadKV(0, 0);
    asm volatile("cp.async.commit_group;" ::: "memory");

    // Warp layout: 4(M) x 4(N)
    const int wmS = (wid >> 2) * 32, wnS = (wid & 3) * 16;
    const int wmP = (wid >> 2) * 32, wnP = (wid & 3) * 32;
    const uint32_t xr     = lid & 7;
    const uint32_t a_row  = lid & 15;
    const uint32_t a_cadd = (lid >= 16) ? 4u : 0u;
    const uint32_t b_row  = ((lid >> 4) << 3) + (lid & 7);
    const uint32_t b_cadd = ((lid >> 3) & 1) * 4u;

    float oacc[2][4][4];
#pragma unroll
    for (int mi = 0; mi < 2; mi++)
#pragma unroll
        for (int nj = 0; nj < 4; nj++)
#pragma unroll
            for (int r = 0; r < 4; r++) oacc[mi][nj][r] = 0.f;

    for (int t = 0; t < SEQ / 64; t++) {
        const int buf = t & 1;
        // All warps must be done with buf^1 (prev iteration's PV reads)
        // BEFORE overwriting it with the next tile's cp.async.
        __syncthreads();
        if (t + 1 < SEQ / 64) {
            loadKV(buf ^ 1, t + 1);
            asm volatile("cp.async.commit_group;" ::: "memory");
            asm volatile("cp.async.wait_group 1;" ::: "memory");
        } else {
            asm volatile("cp.async.wait_group 0;" ::: "memory");
        }
        __syncthreads();

        // ---- S = Q K^T (warp 32x16, k=128) ----
        float sacc[2][2][4];
#pragma unroll
        for (int mi = 0; mi < 2; mi++)
#pragma unroll
            for (int nj = 0; nj < 2; nj++)
#pragma unroll
                for (int r = 0; r < 4; r++) sacc[mi][nj][r] = 0.f;

#pragma unroll
        for (int ks = 0; ks < 16; ks++) {
            const int k0 = ks * 8;
            uint32_t ar[2][4];
#pragma unroll
            for (int mi = 0; mi < 2; mi++) {
                uint32_t addr = sb + AS_QS + (wmS + mi * 16 + a_row) * 512
                              + ((((k0 + a_cadd) >> 2) ^ xr) << 4);
                LDSM_X4(ar[mi][0], ar[mi][1], ar[mi][2], ar[mi][3], addr);
            }
            uint32_t br[4];
            {
                uint32_t addr = KSo[buf] + (wnS + b_row) * 512
                              + ((((k0 + b_cadd) >> 2) ^ xr) << 4);
                LDSM_X4(br[0], br[1], br[2], br[3], addr);
            }
#pragma unroll
            for (int mi = 0; mi < 2; mi++)
#pragma unroll
                for (int nj = 0; nj < 2; nj++)
                    MMA_TF32(sacc[mi][nj], ar[mi][0], ar[mi][1], ar[mi][2], ar[mi][3],
                             br[nj * 2], br[nj * 2 + 1]);
        }

        // store S (scaled) to Ss: 128 rows x 256B, swizzled 16B chunks
#pragma unroll
        for (int mi = 0; mi < 2; mi++) {
            int r0 = wmS + mi * 16 + (lid >> 2);
#pragma unroll
            for (int nj = 0; nj < 2; nj++) {
                int col = wnS + nj * 8 + 2 * (lid & 3);
                uint32_t off = (((uint32_t)(col >> 2) ^ (r0 & 7)) << 4) + (col & 3) * 4;
                *(float2*)(smb + AS_SS + r0 * 256 + off) =
                    make_float2(sacc[mi][nj][0] * SOFTMAX_SCALE, sacc[mi][nj][1] * SOFTMAX_SCALE);
                int r1 = r0 + 8;
                uint32_t off1 = (((uint32_t)(col >> 2) ^ (r1 & 7)) << 4) + (col & 3) * 4;
                *(float2*)(smb + AS_SS + r1 * 256 + off1) =
                    make_float2(sacc[mi][nj][2] * SOFTMAX_SCALE, sacc[mi][nj][3] * SOFTMAX_SCALE);
            }
        }
        __syncthreads();

        // ---- online softmax: 4 threads per row (128 rows); P tf32-rounded ----
        {
            const int r = tid >> 2, seg = tid & 3;
            float4 v[4];
            uint32_t base = (uint32_t)AS_SS + r * 256;
#pragma unroll
            for (int j = 0; j < 4; j++) {
                uint32_t c = (uint32_t)(seg * 4 + j) ^ (r & 7);
                v[j] = *(const float4*)(smb + base + (c << 4));
            }
            float mx = -INFINITY;
#pragma unroll
            for (int j = 0; j < 4; j++)
                mx = fmaxf(mx, fmaxf(fmaxf(v[j].x, v[j].y), fmaxf(v[j].z, v[j].w)));
            mx = fmaxf(mx, __shfl_xor_sync(0xFFFFFFFFu, mx, 1));
            mx = fmaxf(mx, __shfl_xor_sync(0xFFFFFFFFu, mx, 2));
            float m_old = row_m[r];
            float mn = fmaxf(m_old, mx);
            float sum = 0.f;
#pragma unroll
            for (int j = 0; j < 4; j++) {
                v[j].x = __expf(v[j].x - mn);
                v[j].y = __expf(v[j].y - mn);
                v[j].z = __expf(v[j].z - mn);
                v[j].w = __expf(v[j].w - mn);
                sum += v[j].x + v[j].y + v[j].z + v[j].w;
                v[j].x = f2tf32(v[j].x); v[j].y = f2tf32(v[j].y);
                v[j].z = f2tf32(v[j].z); v[j].w = f2tf32(v[j].w);
                uint32_t c = (uint32_t)(seg * 4 + j) ^ (r & 7);
                *(float4*)(smb + base + (c << 4)) = v[j];
            }
            sum += __shfl_xor_sync(0xFFFFFFFFu, sum, 1);
            sum += __shfl_xor_sync(0xFFFFFFFFu, sum, 2);
            if (seg == 0) {
                float f = __expf(m_old - mn);
                row_m[r] = mn;
                row_f[r] = f;
                row_l[r] = row_l[r] * f + sum;
            }
        }
        __syncthreads();

        // ---- rescale O accumulator, then O += P V (warp 32x32) ----
        {
            float f0[2], f1[2];
#pragma unroll
            for (int mi = 0; mi < 2; mi++) {
                f0[mi] = row_f[wmP + mi * 16 + (lid >> 2)];
                f1[mi] = row_f[wmP + mi * 16 + (lid >> 2) + 8];
            }
#pragma unroll
            for (int mi = 0; mi < 2; mi++)
#pragma unroll
                for (int nj = 0; nj < 4; nj++) {
                    oacc[mi][nj][0] *= f0[mi]; oacc[mi][nj][1] *= f0[mi];
                    oacc[mi][nj][2] *= f1[mi]; oacc[mi][nj][3] *= f1[mi];
                }
        }
#pragma unroll
        for (int ks = 0; ks < 8; ks++) {
            const int k0 = ks * 8;
            uint32_t ar[2][4];
#pragma unroll
            for (int mi = 0; mi < 2; mi++) {
                uint32_t addr = sb + AS_SS + (wmP + mi * 16 + a_row) * 256
                              + ((((k0 + a_cadd) >> 2) ^ xr) << 4);
                LDSM_X4(ar[mi][0], ar[mi][1], ar[mi][2], ar[mi][3], addr);
            }
            uint32_t br[2][4];
#pragma unroll
            for (int nb = 0; nb < 2; nb++) {
                uint32_t addr = VSo[buf] + (wnP + nb * 16 + b_row) * 256
                              + ((((k0 + b_cadd) >> 2) ^ xr) << 4);
                LDSM_X4(br[nb][0], br[nb][1], br[nb][2], br[nb][3], addr);
            }
#pragma unroll
            for (int mi = 0; mi < 2; mi++)
#pragma unroll
                for (int nj = 0; nj < 4; nj++)
                    MMA_TF32(oacc[mi][nj], ar[mi][0], ar[mi][1], ar[mi][2], ar[mi][3],
                             br[nj >> 1][(nj & 1) * 2], br[nj >> 1][(nj & 1) * 2 + 1]);
        }
    }

    // ---- epilogue: normalize, round to tf32 (feeds O-proj A operand) ----
#pragma unroll
    for (int mi = 0; mi < 2; mi++) {
        int lr0 = wmP + mi * 16 + (lid >> 2);
        float inv0 = 1.0f / row_l[lr0];
        float inv1 = 1.0f / row_l[lr0 + 8];
        float* O0 = g_O + (size_t)(b * SEQ + q0 + lr0) * DMODEL + h * HDIM;
        float* O1 = g_O + (size_t)(b * SEQ + q0 + lr0 + 8) * DMODEL + h * HDIM;
#pragma unroll
        for (int nj = 0; nj < 4; nj++) {
            int col = wnP + nj * 8 + 2 * (lid & 3);
            *(float2*)(O0 + col) = make_float2(f2tf32(oacc[mi][nj][0] * inv0),
                                               f2tf32(oacc[mi][nj][1] * inv0));
            *(float2*)(O1 + col) = make_float2(f2tf32(oacc[mi][nj][2] * inv1),
                                               f2tf32(oacc[mi][nj][3] * inv1));
        }
    }
}

// ---------------------------------------------------------------------------
extern "C" void kernel_launch(void* const* d_in, const int* in_sizes, int n_in,
                              void* d_out, int out_size)
{
    const float* x  = (const float*)d_in[0];
    const float* Wq = (const float*)d_in[1];
    const float* bq = (const float*)d_in[2];
    const float* Wk = (const float*)d_in[3];
    const float* bk = (const float*)d_in[4];
    const float* Wv = (const float*)d_in[5];
    const float* bv = (const float*)d_in[6];
    const float* Wo = (const float*)d_in[7];
    const float* bo = (const float*)d_in[8];
    float* out = (float*)d_out;

    float *Q, *K, *V, *Vt, *O, *WqT, *WkT, *WvT, *WoT;
    cudaGetSymbolAddress((void**)&Q, g_Q);
    cudaGetSymbolAddress((void**)&K, g_K);
    cudaGetSymbolAddress((void**)&V, g_V);
    cudaGetSymbolAddress((void**)&Vt, g_Vt);
    cudaGetSymbolAddress((void**)&O, g_O);
    cudaGetSymbolAddress((void**)&WqT, g_WqT);
    cudaGetSymbolAddress((void**)&WkT, g_WkT);
    cudaGetSymbolAddress((void**)&WvT, g_WvT);
    cudaGetSymbolAddress((void**)&WoT, g_WoT);

    cudaFuncSetAttribute(tf32_mma_gemm,
                         cudaFuncAttributeMaxDynamicSharedMemorySize, GM_SMEM);
    cudaFuncSetAttribute(attn_mma_kernel,
                         cudaFuncAttributeMaxDynamicSharedMemorySize, ATT_SMEM);

    // Fused prep: weight transposes (tf32-rounded) + x round-copy into g_O
    prep_kernel<<<12288, dim3(32, 8)>>>(x, Wq, Wk, Wv, Wo, O, WqT, WkT, WvT, WoT);

    // Q/K projections with fused RoPE (+round); V projection (+round)
    tf32_mma_gemm<<<dim3(DMODEL/128, ROWS/128), 256, GM_SMEM>>>(O, WqT, bq, Q, ROWS, DMODEL, DMODEL, 2, SOFTMAX_SCALE);
    tf32_mma_gemm<<<dim3(KVD/128,    ROWS/128), 256, GM_SMEM>>>(O, WkT, bk, K, ROWS, KVD, DMODEL, 2, 1.0f);
    tf32_mma_gemm<<<dim3(KVD/128,    ROWS/128), 256, GM_SMEM>>>(O, WvT, bv, V, ROWS, KVD, DMODEL, 1, 1.0f);

    // Transpose V per (b,g) to [dim][seq] for ldmatrix-friendly PV
    v_transpose_kernel<<<dim3(KVD/32, ROWS/32), dim3(32, 8)>>>(V, Vt);

    // Attention (tf32 mma flash, 128-q tiles, 512 threads)
    attn_mma_kernel<<<dim3(BATCH * NHEADS, SEQ / 128), 512, ATT_SMEM>>>();

    // Output projection (final fp32 output, no rounding)
    tf32_mma_gemm<<<dim3(DMODEL/128, ROWS/128), 256, GM_SMEM>>>(O, WoT, bo, out, ROWS, DMODEL, DMODEL, 0, 1.0f);
}

// round 17
// speedup vs baseline: 1.0732x; 1.0732x over previous
#include <cuda_runtime.h>
#include <math.h>
#include <stdint.h>

#define BATCH 4
#define SEQ 1024
#define DMODEL 2048
#define KVD 512
#define NHEADS 16
#define NGROUPS 4
#define HDIM 128
#define ROWS (BATCH*SEQ)           // 4096
#define SOFTMAX_SCALE 0.08838834764831845f   // 1/sqrt(128)

// ---------------------------------------------------------------------------
// Device scratch (no allocation allowed)
// ---------------------------------------------------------------------------
__device__ float g_Q[ROWS*DMODEL];     // 32 MB
__device__ float g_K[ROWS*KVD];        // 8 MB
__device__ float g_V[ROWS*KVD];        // 8 MB
__device__ float g_Vt[BATCH*NGROUPS*HDIM*SEQ]; // 8 MB  [b,g][dim][seq]
__device__ float g_O[ROWS*DMODEL];     // 32 MB (rounded-x before attention, O after)
__device__ float g_WqT[DMODEL*DMODEL]; // 16 MB  [N][K]
__device__ float g_WkT[KVD*DMODEL];    // 4 MB
__device__ float g_WvT[KVD*DMODEL];    // 4 MB
__device__ float g_WoT[DMODEL*DMODEL]; // 16 MB

// ---------------------------------------------------------------------------
// PTX helpers (sm_80-class only — NO tcgen05, harness targets bare sm_103)
// ---------------------------------------------------------------------------
__device__ __forceinline__ uint32_t smem_u32(const void* p) {
    uint32_t a;
    asm("{ .reg .u64 t; cvta.to.shared.u64 t, %1; cvt.u32.u64 %0, t; }"
        : "=r"(a) : "l"(p));
    return a;
}

__device__ __forceinline__ void cp16(uint32_t dst, const void* src) {
    asm volatile("cp.async.cg.shared.global [%0], [%1], 16;" :: "r"(dst), "l"(src));
}

__device__ __forceinline__ float f2tf32(float x) {
    uint32_t u = __float_as_uint(x);
    asm("cvt.rna.tf32.f32 %0, %0;" : "+r"(u));
    return __uint_as_float(u);
}

#define LDSM_X4(r0, r1, r2, r3, addr) \
    asm volatile("ldmatrix.sync.aligned.m8n8.x4.shared.b16 {%0,%1,%2,%3}, [%4];" \
        : "=r"(r0), "=r"(r1), "=r"(r2), "=r"(r3) : "r"(addr))

#define MMA_TF32(d, a0, a1, a2, a3, b0, b1) \
    asm volatile("mma.sync.aligned.m16n8k8.row.col.f32.tf32.tf32.f32 " \
        "{%0,%1,%2,%3}, {%4,%5,%6,%7}, {%8,%9}, {%0,%1,%2,%3};" \
        : "+f"((d)[0]), "+f"((d)[1]), "+f"((d)[2]), "+f"((d)[3]) \
        : "r"(a0), "r"(a1), "r"(a2), "r"(a3), "r"(b0), "r"(b1))

// ---------------------------------------------------------------------------
// Fused prep: 4 weight transposes (tf32-rounded) + x round-copy, ONE launch.
// ---------------------------------------------------------------------------
__device__ __forceinline__ void transpose_block(
    const float* __restrict__ in, float* __restrict__ out,
    int R, int C, int cb, int rb)
{
    __shared__ float t[32][33];
    int c0 = cb * 32, r0 = rb * 32;
    int x = threadIdx.x, y = threadIdx.y;
#pragma unroll
    for (int i = 0; i < 32; i += 8)
        t[y + i][x] = in[(size_t)(r0 + y + i) * C + c0 + x];
    __syncthreads();
#pragma unroll
    for (int i = 0; i < 32; i += 8)
        out[(size_t)(c0 + y + i) * R + r0 + x] = f2tf32(t[x][y + i]);
}

__global__ void prep_kernel(
    const float* __restrict__ x,
    const float* __restrict__ Wq, const float* __restrict__ Wk,
    const float* __restrict__ Wv, const float* __restrict__ Wo,
    float* __restrict__ xr,
    float* __restrict__ WqT, float* __restrict__ WkT,
    float* __restrict__ WvT, float* __restrict__ WoT)
{
    int bid = blockIdx.x;
    if (bid < 4096) {
        transpose_block(Wq, WqT, DMODEL, DMODEL, bid & 63, bid >> 6);
    } else if (bid < 5120) {
        int b = bid - 4096;
        transpose_block(Wk, WkT, DMODEL, KVD, b & 15, b >> 4);
    } else if (bid < 6144) {
        int b = bid - 5120;
        transpose_block(Wv, WvT, DMODEL, KVD, b & 15, b >> 4);
    } else if (bid < 10240) {
        int b = bid - 6144;
        transpose_block(Wo, WoT, DMODEL, DMODEL, b & 63, b >> 6);
    } else {
        int b = bid - 10240;                       // 0..2047
        int tid = threadIdx.y * 32 + threadIdx.x;  // 0..255
        const float4* src = (const float4*)x;
        float4* dst = (float4*)xr;
#pragma unroll
        for (int i = 0; i < 4; i++) {
            int idx = b * 1024 + i * 256 + tid;
            float4 v = src[idx];
            v.x = f2tf32(v.x); v.y = f2tf32(v.y);
            v.z = f2tf32(v.z); v.w = f2tf32(v.w);
            dst[idx] = v;
        }
    }
}

// ---------------------------------------------------------------------------
// V transpose: g_V [4096][512] -> g_Vt [b,g][128 dim][1024 seq]
// ---------------------------------------------------------------------------
__global__ void v_transpose_kernel(const float* __restrict__ in, float* __restrict__ out)
{
    __shared__ float t[32][33];
    int c0 = blockIdx.x * 32, r0 = blockIdx.y * 32;
    int x = threadIdx.x, y = threadIdx.y;  // 32 x 8
#pragma unroll
    for (int i = 0; i < 32; i += 8)
        t[y + i][x] = in[(size_t)(r0 + y + i) * KVD + c0 + x];
    __syncthreads();
#pragma unroll
    for (int i = 0; i < 32; i += 8) {
        int c = c0 + y + i;        // global col: g = c>>7, d = c&127
        int r = r0 + x;            // global row: b = r>>10, s = r&1023
        out[(((size_t)(r >> 10) * NGROUPS + (c >> 7)) * HDIM + (c & 127)) * SEQ + (r & 1023)]
            = t[x][y + i];
    }
}

// ---------------------------------------------------------------------------
// Shared GEMM mainloop body (device inline): computes one 128x128 C tile.
// A[M,K=2048-typed] @ BT[N][K] + bias, with per-call epilogue mode.
// ---------------------------------------------------------------------------
__device__ __forceinline__ void gemm_tile_body(
    const float* __restrict__ A, const float* __restrict__ BT,
    const float* __restrict__ bias, float* __restrict__ C,
    int N, int K, int bm, int bn, int mode, float rope_scale,
    uint32_t sb, int tid)
{
    const int wid = tid >> 5, lid = tid & 31;
    const int wm = (wid >> 2) * 64;
    const int wn = (wid & 3) * 32;

    const uint32_t xr     = lid & 7;
    const uint32_t a_row  = wm + (lid & 15);
    const uint32_t a_cadd = (lid >= 16) ? 4u : 0u;
    const uint32_t b_row  = wn + ((lid >> 4) << 3) + (lid & 7);
    const uint32_t b_cadd = ((lid >> 3) & 1) * 4u;

    float acc[4][4][4];
#pragma unroll
    for (int mi = 0; mi < 4; mi++)
#pragma unroll
        for (int nj = 0; nj < 4; nj++)
#pragma unroll
            for (int r = 0; r < 4; r++) acc[mi][nj][r] = 0.f;

    const int nk = K >> 5;

    auto load_tile = [&](int buf, int ks) {
        const uint32_t abuf = sb + buf * 32768;
        const uint32_t bbuf = abuf + 16384;
        const int k0 = ks * 32;
#pragma unroll
        for (int it = 0; it < 8; it++) {
            int idx = tid + it * 256;
            int c = idx & 7;
            if (idx < 1024) {
                int row = idx >> 3;
                cp16(abuf + row * 128 + ((c ^ (row & 7)) << 4),
                     A + (size_t)(bm + row) * K + k0 + c * 4);
            } else {
                int row = (idx - 1024) >> 3;
                cp16(bbuf + row * 128 + ((c ^ (row & 7)) << 4),
                     BT + (size_t)(bn + row) * K + k0 + c * 4);
            }
        }
        asm volatile("cp.async.commit_group;" ::: "memory");
    };

    load_tile(0, 0);

    for (int ks = 0; ks < nk; ks++) {
        const int buf = ks & 1;
        if (ks + 1 < nk) {
            load_tile(buf ^ 1, ks + 1);
            asm volatile("cp.async.wait_group 1;" ::: "memory");
        } else {
            asm volatile("cp.async.wait_group 0;" ::: "memory");
        }
        __syncthreads();

        const uint32_t abase = sb + buf * 32768;
        const uint32_t bbase = abase + 16384;

#pragma unroll
        for (int s = 0; s < 4; s++) {
            const int k0 = s * 8;
            uint32_t ar[4][4];
#pragma unroll
            for (int mi = 0; mi < 4; mi++) {
                uint32_t addr = abase + (a_row + mi * 16) * 128
                              + ((((k0 + a_cadd) >> 2) ^ xr) << 4);
                LDSM_X4(ar[mi][0], ar[mi][1], ar[mi][2], ar[mi][3], addr);
            }
            uint32_t br[2][4];
#pragma unroll
            for (int nb = 0; nb < 2; nb++) {
                uint32_t addr = bbase + (b_row + nb * 16) * 128
                              + ((((k0 + b_cadd) >> 2) ^ xr) << 4);
                LDSM_X4(br[nb][0], br[nb][1], br[nb][2], br[nb][3], addr);
            }
#pragma unroll
            for (int mi = 0; mi < 4; mi++)
#pragma unroll
                for (int nj = 0; nj < 4; nj++) {
                    uint32_t b0 = br[nj >> 1][(nj & 1) * 2];
                    uint32_t b1 = br[nj >> 1][(nj & 1) * 2 + 1];
                    MMA_TF32(acc[mi][nj], ar[mi][0], ar[mi][1], ar[mi][2], ar[mi][3], b0, b1);
                }
        }
        __syncthreads();
    }

    const int tq = lid >> 2;
    const int tc = (lid & 3) * 2;
#pragma unroll
    for (int mi = 0; mi < 4; mi++) {
        const int row = bm + wm + mi * 16 + tq;
#pragma unroll
        for (int nj = 0; nj < 4; nj++) {
            const int col = bn + wn + nj * 8 + tc;   // always even
            float2 bv = *(const float2*)(bias + col);
            float2 o0 = { acc[mi][nj][0] + bv.x, acc[mi][nj][1] + bv.y };
            float2 o1 = { acc[mi][nj][2] + bv.x, acc[mi][nj][3] + bv.y };
            if (mode == 2) {
                int i = (col & 127) >> 1;
                float freq = exp2f(-((float)(2 * i) / 128.0f) * 13.287712379549449f);
                float s0, c0, s1, c1;
                sincosf((float)(row & (SEQ - 1)) * freq, &s0, &c0);
                sincosf((float)((row + 8) & (SEQ - 1)) * freq, &s1, &c1);
                float x0 = o0.x, y0 = o0.y, x1 = o1.x, y1 = o1.y;
                o0.x = (x0 * c0 - y0 * s0) * rope_scale;
                o0.y = (x0 * s0 + y0 * c0) * rope_scale;
                o1.x = (x1 * c1 - y1 * s1) * rope_scale;
                o1.y = (x1 * s1 + y1 * c1) * rope_scale;
            }
            if (mode != 0) {
                o0.x = f2tf32(o0.x); o0.y = f2tf32(o0.y);
                o1.x = f2tf32(o1.x); o1.y = f2tf32(o1.y);
            }
            *(float2*)(C + (size_t)row * N + col)       = o0;
            *(float2*)(C + (size_t)(row + 8) * N + col) = o1;
        }
    }
}

#define GM_SMEM 65536

// ---------------------------------------------------------------------------
// Fused QKV projection: one launch, 2 CTAs/SM.
// blockIdx.x: 0..15 -> Q cols (RoPE+scale), 16..19 -> K cols (RoPE), 20..23 -> V
// blockIdx.y: M tile (32).
// ---------------------------------------------------------------------------
__global__ __launch_bounds__(256, 2) void qkv_gemm(
    const float* __restrict__ A,
    const float* __restrict__ bq, const float* __restrict__ bk,
    const float* __restrict__ bv)
{
    extern __shared__ char sm[];
    const uint32_t sb = smem_u32(sm);
    const int tid = threadIdx.x;
    const int bm = blockIdx.y * 128;
    const int t = blockIdx.x;

    if (t < 16) {
        gemm_tile_body(A, g_WqT, bq, g_Q, DMODEL, DMODEL, bm, t * 128,
                       2, SOFTMAX_SCALE, sb, tid);
    } else if (t < 20) {
        gemm_tile_body(A, g_WkT, bk, g_K, KVD, DMODEL, bm, (t - 16) * 128,
                       2, 1.0f, sb, tid);
    } else {
        gemm_tile_body(A, g_WvT, bv, g_V, KVD, DMODEL, bm, (t - 20) * 128,
                       1, 1.0f, sb, tid);
    }
}

// ---------------------------------------------------------------------------
// O projection (plain fp32 out), 2 CTAs/SM.
// ---------------------------------------------------------------------------
__global__ __launch_bounds__(256, 2) void oproj_gemm(
    const float* __restrict__ A, const float* __restrict__ bo,
    float* __restrict__ C)
{
    extern __shared__ char sm[];
    const uint32_t sb = smem_u32(sm);
    gemm_tile_body(A, g_WoT, bo, C, DMODEL, DMODEL,
                   blockIdx.y * 128, blockIdx.x * 128, 0, 1.0f,
                   sb, threadIdx.x);
}

// ---------------------------------------------------------------------------
// Tensor-core flash attention, BM=128 q-rows per CTA, 256 threads (R14 config)
// Smem: Qs 128x512B @0; Ks 64x512B x2; Vt 128x256B x2; Ss 128x256B; stats
// Warps: 4(M) x 2(N). S warp-tile 32x32; PV warp-tile 32x64.
// ---------------------------------------------------------------------------
#define AS_QS 0
#define AS_KS0 65536
#define AS_KS1 98304
#define AS_VS0 131072
#define AS_VS1 163840
#define AS_SS 196608
#define AS_STAT 229376
#define ATT_SMEM (AS_STAT + 1536)   // 230912 bytes

__global__ __launch_bounds__(256, 1) void attn_mma_kernel()
{
    extern __shared__ char smb[];
    const uint32_t sb = smem_u32(smb);
    float* row_m = (float*)(smb + AS_STAT);
    float* row_l = row_m + 128;
    float* row_f = row_l + 128;

    const int tid = threadIdx.x;
    const int wid = tid >> 5, lid = tid & 31;
    const int b = blockIdx.x >> 4;
    const int h = blockIdx.x & 15;
    const int g = h >> 2;
    const int q0 = blockIdx.y * 128;

    const float* Qg  = g_Q + (size_t)(b * SEQ + q0) * DMODEL + h * HDIM;
    const float* Kg  = g_K + (size_t)(b * SEQ) * KVD + g * HDIM;
    const float* Vtg = g_Vt + ((size_t)(b * NGROUPS + g)) * HDIM * SEQ;

    const uint32_t KSo[2] = {sb + AS_KS0, sb + AS_KS1};
    const uint32_t VSo[2] = {sb + AS_VS0, sb + AS_VS1};

    if (tid < 128) { row_m[tid] = -INFINITY; row_l[tid] = 0.f; }

    // Q: 128 rows x 512B swizzled
#pragma unroll
    for (int it = 0; it < 16; it++) {
        int idx = tid + it * 256;
        int r = idx >> 5, c = idx & 31;
        cp16(sb + AS_QS + r * 512 + ((c ^ (r & 7)) << 4),
             Qg + (size_t)r * DMODEL + c * 4);
    }
    auto loadKV = [&](int buf, int t) {
        const float* Kt = Kg + (size_t)(t * 64) * KVD;
        const float* Vt = Vtg + t * 64;
#pragma unroll
        for (int it = 0; it < 8; it++) {
            int idx = tid + it * 256;
            int r = idx >> 5, c = idx & 31;
            cp16(KSo[buf] + r * 512 + ((c ^ (r & 7)) << 4),
                 Kt + (size_t)r * KVD + c * 4);
        }
#pragma unroll
        for (int it = 0; it < 8; it++) {
            int idx = tid + it * 256;
            int r = idx >> 4, c = idx & 15;
            cp16(VSo[buf] + r * 256 + (((uint32_t)c ^ (r & 7)) << 4),
                 Vt + (size_t)r * SEQ + c * 4);
        }
    };
    loadKV(0, 0);
    asm volatile("cp.async.commit_group;" ::: "memory");

    const int wmS = (wid >> 1) * 32, wnS = (wid & 1) * 32;
    const int wmP = (wid >> 1) * 32, wnP = (wid & 1) * 64;
    const uint32_t xr     = lid & 7;
    const uint32_t a_row  = lid & 15;
    const uint32_t a_cadd = (lid >= 16) ? 4u : 0u;
    const uint32_t b_row  = ((lid >> 4) << 3) + (lid & 7);
    const uint32_t b_cadd = ((lid >> 3) & 1) * 4u;

    float oacc[2][8][4];
#pragma unroll
    for (int mi = 0; mi < 2; mi++)
#pragma unroll
        for (int nj = 0; nj < 8; nj++)
#pragma unroll
            for (int r = 0; r < 4; r++) oacc[mi][nj][r] = 0.f;

    for (int t = 0; t < SEQ / 64; t++) {
        const int buf = t & 1;
        __syncthreads();
        if (t + 1 < SEQ / 64) {
            loadKV(buf ^ 1, t + 1);
            asm volatile("cp.async.commit_group;" ::: "memory");
            asm volatile("cp.async.wait_group 1;" ::: "memory");
        } else {
            asm volatile("cp.async.wait_group 0;" ::: "memory");
        }
        __syncthreads();

        // ---- S = Q K^T (warp 32x32, k=128) ----
        float sacc[2][4][4];
#pragma unroll
        for (int mi = 0; mi < 2; mi++)
#pragma unroll
            for (int nj = 0; nj < 4; nj++)
#pragma unroll
                for (int r = 0; r < 4; r++) sacc[mi][nj][r] = 0.f;

#pragma unroll
        for (int ks = 0; ks < 16; ks++) {
            const int k0 = ks * 8;
            uint32_t ar[2][4];
#pragma unroll
            for (int mi = 0; mi < 2; mi++) {
                uint32_t addr = sb + AS_QS + (wmS + mi * 16 + a_row) * 512
                              + ((((k0 + a_cadd) >> 2) ^ xr) << 4);
                LDSM_X4(ar[mi][0], ar[mi][1], ar[mi][2], ar[mi][3], addr);
            }
            uint32_t br[2][4];
#pragma unroll
            for (int nb = 0; nb < 2; nb++) {
                uint32_t addr = KSo[buf] + (wnS + nb * 16 + b_row) * 512
                              + ((((k0 + b_cadd) >> 2) ^ xr) << 4);
                LDSM_X4(br[nb][0], br[nb][1], br[nb][2], br[nb][3], addr);
            }
#pragma unroll
            for (int mi = 0; mi < 2; mi++)
#pragma unroll
                for (int nj = 0; nj < 4; nj++)
                    MMA_TF32(sacc[mi][nj], ar[mi][0], ar[mi][1], ar[mi][2], ar[mi][3],
                             br[nj >> 1][(nj & 1) * 2], br[nj >> 1][(nj & 1) * 2 + 1]);
        }

        // store S (scaled) to Ss: 128 rows x 256B, swizzled 16B chunks
#pragma unroll
        for (int mi = 0; mi < 2; mi++) {
            int r0 = wmS + mi * 16 + (lid >> 2);
#pragma unroll
            for (int nj = 0; nj < 4; nj++) {
                int col = wnS + nj * 8 + 2 * (lid & 3);
                uint32_t off = (((uint32_t)(col >> 2) ^ (r0 & 7)) << 4) + (col & 3) * 4;
                *(float2*)(smb + AS_SS + r0 * 256 + off) =
                    make_float2(sacc[mi][nj][0] * SOFTMAX_SCALE, sacc[mi][nj][1] * SOFTMAX_SCALE);
                int r1 = r0 + 8;
                uint32_t off1 = (((uint32_t)(col >> 2) ^ (r1 & 7)) << 4) + (col & 3) * 4;
                *(float2*)(smb + AS_SS + r1 * 256 + off1) =
                    make_float2(sacc[mi][nj][2] * SOFTMAX_SCALE, sacc[mi][nj][3] * SOFTMAX_SCALE);
            }
        }
        __syncthreads();

        // ---- online softmax: 2 threads per row (128 rows); P tf32-rounded ----
        {
            const int r = tid >> 1, seg = tid & 1;
            float4 v[8];
            uint32_t base = (uint32_t)AS_SS + r * 256;
#pragma unroll
            for (int j = 0; j < 8; j++) {
                uint32_t c = (uint32_t)(seg * 8 + j) ^ (r & 7);
                v[j] = *(const float4*)(smb + base + (c << 4));
            }
            float mx = -INFINITY;
#pragma unroll
            for (int j = 0; j < 8; j++)
                mx = fmaxf(mx, fmaxf(fmaxf(v[j].x, v[j].y), fmaxf(v[j].z, v[j].w)));
            mx = fmaxf(mx, __shfl_xor_sync(0xFFFFFFFFu, mx, 1));
            float m_old = row_m[r];
            float mn = fmaxf(m_old, mx);
            float sum = 0.f;
#pragma unroll
            for (int j = 0; j < 8; j++) {
                v[j].x = __expf(v[j].x - mn);
                v[j].y = __expf(v[j].y - mn);
                v[j].z = __expf(v[j].z - mn);
                v[j].w = __expf(v[j].w - mn);
                sum += v[j].x + v[j].y + v[j].z + v[j].w;
                v[j].x = f2tf32(v[j].x); v[j].y = f2tf32(v[j].y);
                v[j].z = f2tf32(v[j].z); v[j].w = f2tf32(v[j].w);
                uint32_t c = (uint32_t)(seg * 8 + j) ^ (r & 7);
                *(float4*)(smb + base + (c << 4)) = v[j];
            }
            sum += __shfl_xor_sync(0xFFFFFFFFu, sum, 1);
            if (seg == 0) {
                float f = __expf(m_old - mn);
                row_m[r] = mn;
                row_f[r] = f;
                row_l[r] = row_l[r] * f + sum;
            }
        }
        __syncthreads();

        // ---- rescale O accumulator, then O += P V ----
        {
            float f0[2], f1[2];
#pragma unroll
            for (int mi = 0; mi < 2; mi++) {
                f0[mi] = row_f[wmP + mi * 16 + (lid >> 2)];
                f1[mi] = row_f[wmP + mi * 16 + (lid >> 2) + 8];
            }
#pragma unroll
            for (int mi = 0; mi < 2; mi++)
#pragma unroll
                for (int nj = 0; nj < 8; nj++) {
                    oacc[mi][nj][0] *= f0[mi]; oacc[mi][nj][1] *= f0[mi];
                    oacc[mi][nj][2] *= f1[mi]; oacc[mi][nj][3] *= f1[mi];
                }
        }
#pragma unroll
        for (int ks = 0; ks < 8; ks++) {
            const int k0 = ks * 8;
            uint32_t ar[2][4];
#pragma unroll
            for (int mi = 0; mi < 2; mi++) {
                uint32_t addr = sb + AS_SS + (wmP + mi * 16 + a_row) * 256
                              + ((((k0 + a_cadd) >> 2) ^ xr) << 4);
                LDSM_X4(ar[mi][0], ar[mi][1], ar[mi][2], ar[mi][3], addr);
            }
            uint32_t br[4][4];
#pragma unroll
            for (int nb = 0; nb < 4; nb++) {
                uint32_t addr = VSo[buf] + (wnP + nb * 16 + b_row) * 256
                              + ((((k0 + b_cadd) >> 2) ^ xr) << 4);
                LDSM_X4(br[nb][0], br[nb][1], br[nb][2], br[nb][3], addr);
            }
#pragma unroll
            for (int mi = 0; mi < 2; mi++)
#pragma unroll
                for (int nj = 0; nj < 8; nj++)
                    MMA_TF32(oacc[mi][nj], ar[mi][0], ar[mi][1], ar[mi][2], ar[mi][3],
                             br[nj >> 1][(nj & 1) * 2], br[nj >> 1][(nj & 1) * 2 + 1]);
        }
    }

    // ---- epilogue: normalize, round to tf32 (feeds O-proj A operand) ----
#pragma unroll
    for (int mi = 0; mi < 2; mi++) {
        int lr0 = wmP + mi * 16 + (lid >> 2);
        float inv0 = 1.0f / row_l[lr0];
        float inv1 = 1.0f / row_l[lr0 + 8];
        float* O0 = g_O + (size_t)(b * SEQ + q0 + lr0) * DMODEL + h * HDIM;
        float* O1 = g_O + (size_t)(b * SEQ + q0 + lr0 + 8) * DMODEL + h * HDIM;
#pragma unroll
        for (int nj = 0; nj < 8; nj++) {
            int col = wnP + nj * 8 + 2 * (lid & 3);
            *(float2*)(O0 + col) = make_float2(f2tf32(oacc[mi][nj][0] * inv0),
                                               f2tf32(oacc[mi][nj][1] * inv0));
            *(float2*)(O1 + col) = make_float2(f2tf32(oacc[mi][nj][2] * inv1),
                                               f2tf32(oacc[mi][nj][3] * inv1));
        }
    }
}

// ---------------------------------------------------------------------------
extern "C" void kernel_launch(void* const* d_in, const int* in_sizes, int n_in,
                              void* d_out, int out_size)
{
    const float* x  = (const float*)d_in[0];
    const float* Wq = (const float*)d_in[1];
    const float* bq = (const float*)d_in[2];
    const float* Wk = (const float*)d_in[3];
    const float* bk = (const float*)d_in[4];
    const float* Wv = (const float*)d_in[5];
    const float* bv = (const float*)d_in[6];
    const float* Wo = (const float*)d_in[7];
    const float* bo = (const float*)d_in[8];
    float* out = (float*)d_out;

    float *Q, *K, *V, *Vt, *O, *WqT, *WkT, *WvT, *WoT;
    cudaGetSymbolAddress((void**)&Q, g_Q);
    cudaGetSymbolAddress((void**)&K, g_K);
    cudaGetSymbolAddress((void**)&V, g_V);
    cudaGetSymbolAddress((void**)&Vt, g_Vt);
    cudaGetSymbolAddress((void**)&O, g_O);
    cudaGetSymbolAddress((void**)&WqT, g_WqT);
    cudaGetSymbolAddress((void**)&WkT, g_WkT);
    cudaGetSymbolAddress((void**)&WvT, g_WvT);
    cudaGetSymbolAddress((void**)&WoT, g_WoT);

    cudaFuncSetAttribute(qkv_gemm,
                         cudaFuncAttributeMaxDynamicSharedMemorySize, GM_SMEM);
    cudaFuncSetAttribute(oproj_gemm,
                         cudaFuncAttributeMaxDynamicSharedMemorySize, GM_SMEM);
    cudaFuncSetAttribute(attn_mma_kernel,
                         cudaFuncAttributeMaxDynamicSharedMemorySize, ATT_SMEM);

    // Fused prep: weight transposes (tf32-rounded) + x round-copy into g_O
    prep_kernel<<<12288, dim3(32, 8)>>>(x, Wq, Wk, Wv, Wo, O, WqT, WkT, WvT, WoT);

    // Fused QKV projection (RoPE on Q/K in epilogue), one launch, 2 CTA/SM
    qkv_gemm<<<dim3(24, ROWS/128), 256, GM_SMEM>>>(O, bq, bk, bv);

    // Transpose V per (b,g) to [dim][seq] for ldmatrix-friendly PV
    v_transpose_kernel<<<dim3(KVD/32, ROWS/32), dim3(32, 8)>>>(V, Vt);

    // Attention (tf32 mma flash, 128-q tiles, 256 threads)
    attn_mma_kernel<<<dim3(BATCH * NHEADS, SEQ / 128), 256, ATT_SMEM>>>();

    // Output projection (final fp32 output, no rounding)
    oproj_gemm<<<dim3(DMODEL/128, ROWS/128), 256, GM_SMEM>>>(O, bo, out);
}